// round 15
// baseline (speedup 1.0000x reference)
#include <cuda_runtime.h>

#define NPIX   289
#define STEPS  512
#define PP     20           // padded tile pitch
#define TILE   384
#define NT     640          // warps 0-18: 578 pixel threads (2/pixel); warp 19: selection
#define HBPS   10           // hbias per-thread row stride (u64) -> 80B, bank-clean

typedef unsigned long long u64;
typedef unsigned int u32;

__device__ __forceinline__ u64 ffma2(u64 a, u64 b, u64 c){
    u64 d; asm("fma.rn.f32x2 %0, %1, %2, %3;" : "=l"(d) : "l"(a), "l"(b), "l"(c)); return d;
}
__device__ __forceinline__ u64 fadd2(u64 a, u64 b){
    u64 d; asm("add.rn.f32x2 %0, %1, %2;" : "=l"(d) : "l"(a), "l"(b)); return d;
}
__device__ __forceinline__ u64 pack2(float x, float y){
    u64 r; asm("mov.b64 %0, {%1, %2};" : "=l"(r)
               : "r"(__float_as_uint(x)), "r"(__float_as_uint(y)));
    return r;
}
__device__ __forceinline__ void unpack2(u64 v, float &x, float &y){
    u32 a, b; asm("mov.b64 {%0, %1}, %2;" : "=r"(a), "=r"(b) : "l"(v));
    x = __uint_as_float(a); y = __uint_as_float(b);
}
__device__ __forceinline__ int imax(int a, int b){ return a > b ? a : b; }
__device__ __forceinline__ u32 smem_addr_u32(const void* p){
    u32 a; asm("{ .reg .u64 t; cvta.to.shared.u64 t, %1; cvt.u32.u64 %0, t; }"
               : "=r"(a) : "l"(p));
    return a;
}
__device__ __forceinline__ void dsmem_st64(u32 addr, u64 v){
    asm volatile("st.shared::cluster.u64 [%0], %1;" :: "r"(addr), "l"(v) : "memory");
}
__device__ __forceinline__ void mbar_init(u32 addr, u32 cnt){
    asm volatile("mbarrier.init.shared.b64 [%0], %1;" :: "r"(addr), "r"(cnt) : "memory");
}
__device__ __forceinline__ void mbar_arrive_remote(u32 addr){
    asm volatile("mbarrier.arrive.release.cluster.shared::cluster.b64 _, [%0];"
                 :: "r"(addr) : "memory");
}
__device__ __forceinline__ void mbar_wait(u32 addr, u32 phase){
    asm volatile(
        "{\n\t"
        ".reg .pred P1;\n\t"
        "WAIT_%=:\n\t"
        "mbarrier.try_wait.parity.acquire.cluster.shared::cta.b64 P1, [%0], %1;\n\t"
        "@P1 bra.uni DONE_%=;\n\t"
        "bra.uni WAIT_%=;\n\t"
        "DONE_%=:\n\t"
        "}"
        :: "r"(addr), "r"(phase) : "memory");
}
#define CLUSTER_SYNC() do { \
    asm volatile("barrier.cluster.arrive.aligned;" ::: "memory"); \
    asm volatile("barrier.cluster.wait.aligned;"   ::: "memory"); \
} while(0)

/* u64 layout: w1I[16][10] | f2I[16][4] | s12[384] | pbuf[2][289][2] | hbr[578][10] | mbar[2] */
#define OFF_W1I  0
#define OFF_F2I  (OFF_W1I + 160)
#define OFF_S12  (OFF_F2I + 64)
#define OFF_PBUF (OFF_S12 + TILE)
#define OFF_HBR  (OFF_PBUF + 2*NPIX*2)
#define OFF_MBAR (OFF_HBR + 578*HBPS)
#define NU64     (OFF_MBAR + 2)
#define NF       (3*TILE + 20)                    /* sc0, x0t, sct, wsum */
#define NU32     (324)                            /* bitsv(320) + sel(4) */
#define SMEM_BYTES (NU64*8 + NF*4 + NU32*4)

// overlap work: ch1/ch2 packed stencil + ch0 neighbor prefetch
__device__ __forceinline__ void overlap_work(
    const u64* __restrict__ s12, const float* __restrict__ sc0, int idx,
    u64& Y1, u64& Y2, u64& Y4, u64& Y5, u64& Y7, u64& Y8,
    float& y1v, float& y2v, float* pn)
{
    u64 g00=s12[idx-PP-1], g01=s12[idx-PP], g02=s12[idx-PP+1];
    u64 g10=s12[idx-1],    g11=s12[idx],    g12=s12[idx+1];
    u64 g20=s12[idx+PP-1], g21=s12[idx+PP], g22=s12[idx+PP+1];
    float a00,c00; unpack2(g00,a00,c00);
    float a01,c01; unpack2(g01,a01,c01);
    float a02,c02; unpack2(g02,a02,c02);
    float a10,c10; unpack2(g10,a10,c10);
    float a11,c11; unpack2(g11,a11,c11);
    float a12,c12; unpack2(g12,a12,c12);
    float a20,c20; unpack2(g20,a20,c20);
    float a21,c21; unpack2(g21,a21,c21);
    float a22,c22; unpack2(g22,a22,c22);
    y1v = a11;  y2v = c11;
    float y4 = (a02 - a00 + 2.f*(a12 - a10) + a22 - a20) * 0.125f;
    float y7 = (a20 - a00 + 2.f*(a21 - a01) + a22 - a02) * 0.125f;
    float y5 = (c02 - c00 + 2.f*(c12 - c10) + c22 - c20) * 0.125f;
    float y8 = (c20 - c00 + 2.f*(c21 - c01) + c22 - c02) * 0.125f;
    Y1 = pack2(y1v,y1v); Y2 = pack2(y2v,y2v);
    Y4 = pack2(y4,y4);   Y5 = pack2(y5,y5);
    Y7 = pack2(y7,y7);   Y8 = pack2(y8,y8);
    pn[0]=sc0[idx-PP-1]; pn[1]=sc0[idx-PP]; pn[2]=sc0[idx-PP+1];
    pn[3]=sc0[idx-1];    pn[4]=sc0[idx+1];
    pn[5]=sc0[idx+PP-1]; pn[6]=sc0[idx+PP]; pn[7]=sc0[idx+PP+1];
}

__global__ void __launch_bounds__(NT, 1) __cluster_dims__(2, 1, 1) ca_kernel(
    const float* __restrict__ cell, const float* __restrict__ food,
    const float* __restrict__ fc1w, const float* __restrict__ fc1b,
    const float* __restrict__ fc2w, const float* __restrict__ fc2b,
    float* __restrict__ out)
{
    extern __shared__ u64 sm[];
    u64*   w1I  = sm + OFF_W1I;        // own-rank fc1 rows, slot=2t+hh
    u64*   f2I  = sm + OFF_F2I;        // own-rank fc2 rows, slot=2t+hh
    u64*   s12  = sm + OFF_S12;        // packed (c1,c2) tile
    u64*   pbuf = sm + OFF_PBUF;       // [2][NPIX][2] peer partial mailbox
    u64*   hbr  = sm + OFF_HBR;        // [578][HBPS] per-thread hbias rows
    u64*   mbar = sm + OFF_MBAR;       // 2 mbarriers (double buffer)
    float* fb   = (float*)(sm + NU64);
    float* sc0  = fb;                  // unmasked c0p tile
    float* x0t  = fb + TILE;
    float* sct  = fb + 2*TILE;         // scent (prologue only)
    float* wsum = fb + 3*TILE;         // 20
    u32* bitsv  = (u32*)(wsum + 20);   // 320 (padded with zeros)
    u32* sel    = bitsv + 320;         // [0]=kth bits, [1]=living (read as u64)

    const int  tid  = threadIdx.x;
    const int  lane = tid & 31;
    u32 rank; asm("mov.u32 %0, %%cluster_ctarank;" : "=r"(rank));
    const int  b    = blockIdx.x >> 1;
    const int  p    = tid >> 1;
    const int  hh   = tid & 1;
    const bool act  = tid < 2*NPIX;
    const int  prow = p / 17, pcol = p % 17;
    const int  idx  = (prow + 1) * PP + (pcol + 1);
    const int  row  = tid * HBPS;      // private hbias row

    for (int i = tid; i < TILE; i += NT){
        sc0[i]=0.f; x0t[i]=0.f; sct[i]=0.f; s12[i]=0ull;
    }
    if (tid < 320) bitsv[tid] = 0u;

    // ---- weight interleave: own rank's 16 pair-rows, slot = 2t + hh ----
    if (tid < 160){
        const int cjmap[9] = {0,1,2,4,5,6,8,9,10};
        int s = tid / 10, j = tid % 10;
        int q = (int)(rank << 4) + (s & 1) * 8 + (s >> 1);
        float wa = 0.f, wb = 0.f;
        if (j < 9){
            wa = fc1w[(2*q)   * 12 + cjmap[j]];
            wb = fc1w[(2*q+1) * 12 + cjmap[j]];
        }
        w1I[tid] = pack2(wa, wb);
    }
    if (tid < 64){
        int s = tid >> 2, o2 = tid & 3;
        int q = (int)(rank << 4) + (s & 1) * 8 + (s >> 1);
        f2I[tid] = pack2(fc2w[o2*64 + 2*q], fc2w[o2*64 + 2*q + 1]);
    }
    if (tid == 0){
        mbar_init(smem_addr_u32(mbar),     NPIX);
        mbar_init(smem_addr_u32(mbar + 1), NPIX);
    }
    const float b2r0 = fc2b[0], b2r1 = fc2b[1], b2r2 = fc2b[2], b2r3 = fc2b[3];
    __syncthreads();

    // ---- load cell, compute scent (constant). FULL state in BOTH CTAs ----
    float c0v = 0.f, scv = 0.f;
    if (act){
        c0v = cell[(b*4 + 0)*NPIX + p];
        float cv1 = cell[(b*4 + 1)*NPIX + p];
        float cv2 = cell[(b*4 + 2)*NPIX + p];
        if (hh == 0){ sc0[idx] = c0v; s12[idx] = pack2(cv1, cv2); }
        const float SW[5][5] = {
            {0.f,   0.125f,0.25f,0.125f,0.f  },
            {0.125f,0.25f, 0.5f, 0.25f, 0.125f},
            {0.25f, 0.5f,  1.0f, 0.5f,  0.25f },
            {0.125f,0.25f, 0.5f, 0.25f, 0.125f},
            {0.f,   0.125f,0.25f,0.125f,0.f  }};
        float s = 0.f;
        #pragma unroll
        for (int di = 0; di < 5; di++)
            #pragma unroll
            for (int dj = 0; dj < 5; dj++){
                int rr2 = prow + di - 2, c2 = pcol + dj - 2;
                if (rr2 >= 0 && rr2 < 17 && c2 >= 0 && c2 < 17)
                    s += SW[di][dj] * food[b*NPIX + rr2*17 + c2];
            }
        scv = s;
        if (hh == 0) sct[idx] = s;
    }
    int living0 = __syncthreads_count(act && hh == 0 && (c0v > 0.1f));
    if (tid == 0){ *(u64*)sel = ((u64)(u32)living0 << 32); }
    u32 kthW = 0u;
    int livW = living0;
    u64 selv = ((u64)(u32)living0 << 32);

    // ---- hbias fold: own 8 pairs (q = rank*16 + hh*8 + t) ----
    if (act){
        float m00=sct[idx-PP-1], m01=sct[idx-PP], m02=sct[idx-PP+1];
        float m10=sct[idx-1],                     m12=sct[idx+1];
        float m20=sct[idx+PP-1], m21=sct[idx+PP], m22=sct[idx+PP+1];
        float dsx = (m02 - m00 + 2.f*(m12 - m10) + m22 - m20) * 0.125f;
        float dsy = (m20 - m00 + 2.f*(m21 - m01) + m22 - m02) * 0.125f;
        #pragma unroll
        for (int t = 0; t < 8; t++){
            int q = (int)(rank << 4) + hh * 8 + t;
            float h0 = fc1b[2*q]   + fc1w[(2*q)*12+3]  *scv
                     + fc1w[(2*q)*12+7]  *dsx + fc1w[(2*q)*12+11]  *dsy;
            float h1 = fc1b[2*q+1] + fc1w[(2*q+1)*12+3]*scv
                     + fc1w[(2*q+1)*12+7]*dsx + fc1w[(2*q+1)*12+11]*dsy;
            hbr[row + t] = pack2(h0, h1);
        }
    }
    __syncthreads();

    // ---- DSMEM addressing ----
    const u32 my_pb = smem_addr_u32(pbuf);
    const u32 my_mb = smem_addr_u32(mbar);
    u32 peer_pb, peer_mb;
    asm("mapa.shared::cluster.u32 %0, %1, %2;" : "=r"(peer_pb) : "r"(my_pb), "r"(rank ^ 1u));
    asm("mapa.shared::cluster.u32 %0, %1, %2;" : "=r"(peer_mb) : "r"(my_mb), "r"(rank ^ 1u));

    // peer mbarriers initialized before any cross-CTA store/arrive
    CLUSTER_SYNC();

    // ---- prologue overlap ----
    u64 Y1=0,Y2=0,Y4=0,Y5=0,Y7=0,Y8=0;
    float y1v=0.f, y2v=0.f;
    float pn[8] = {0,0,0,0,0,0,0,0};
    if (act) overlap_work(s12, sc0, idx, Y1,Y2,Y4,Y5,Y7,Y8, y1v,y2v, pn);

    float c0pPrev = c0v;
    u32   bitsPrev = __float_as_uint(c0v);
    float c1n = 0.f, c2n = 0.f, c3n = 0.f;
    int par = 0;
    u32 ph0 = 0, ph1 = 0;

    for (int st = 0; st < STEPS; st++){
        const u32 kth = (u32)selv;

        float x0=0.f, x1=0.f, x2=0.f, x3=0.f;
        bool  pre = false;
        u64 d0=0ull, d1=0ull, d2=0ull, d3=0ull;
        float y0 = 0.f;
        bool same = true;

        if (act){
            // apply mask to prefetched ch0 neighbors (pure ALU)
            u32 mb[8]; float n[8];
            #pragma unroll
            for (int i = 0; i < 8; i++){
                u32 q = __float_as_uint(pn[i]);
                mb[i] = (q >= kth) ? q : 0u;
                n[i]  = __uint_as_float(mb[i]);
            }
            u32 mc = (bitsPrev >= kth) ? bitsPrev : 0u;
            y0 = __uint_as_float(mc);
            int mi = imax(imax(imax((int)mb[0],(int)mb[1]), imax((int)mb[2],(int)mb[3])),
                          imax(imax((int)mb[4],(int)mb[5]), imax(imax((int)mb[6],(int)mb[7]),(int)mc)));
            pre = mi > 0x3DCCCCCD;   // > 0.1f
            float y3 = (n[2] - n[0] + 2.f*(n[4] - n[3]) + n[7] - n[5]) * 0.125f;
            float y6 = (n[5] - n[0] + 2.f*(n[6] - n[1]) + n[7] - n[2]) * 0.125f;

            u64 Y0=pack2(y0,y0), Y3=pack2(y3,y3), Y6=pack2(y6,y6);

            // MLP over OWN 8 hidden pairs (slots 4*t2 + 2*tt + hh)
            #pragma unroll
            for (int t2 = 0; t2 < 4; t2++){
                ulonglong2 hbp = *(const ulonglong2*)(hbr + row + 2*t2);
                #pragma unroll
                for (int tt = 0; tt < 2; tt++){
                    const int slot = 4*t2 + 2*tt + hh;
                    u64 acc = tt ? hbp.y : hbp.x;
                    const ulonglong2* wr = reinterpret_cast<const ulonglong2*>(w1I + slot*10);
                    ulonglong2 wA = wr[0], wB = wr[1], wC = wr[2], wD = wr[3], wE = wr[4];
                    acc = ffma2(wA.x, Y0, acc);
                    acc = ffma2(wA.y, Y1, acc);
                    acc = ffma2(wB.x, Y2, acc);
                    acc = ffma2(wB.y, Y3, acc);
                    acc = ffma2(wC.x, Y4, acc);
                    acc = ffma2(wC.y, Y5, acc);
                    acc = ffma2(wD.x, Y6, acc);
                    acc = ffma2(wD.y, Y7, acc);
                    acc = ffma2(wE.x, Y8, acc);
                    // relu via signed-int max on packed halves (ALU pipe)
                    float lo, hi; unpack2(acc, lo, hi);
                    int li  = imax((int)__float_as_uint(lo), 0);
                    int hi2 = imax((int)__float_as_uint(hi), 0);
                    acc = pack2(__uint_as_float((u32)li), __uint_as_float((u32)hi2));
                    const ulonglong2* fr = reinterpret_cast<const ulonglong2*>(f2I + slot*4);
                    ulonglong2 fA = fr[0], fB = fr[1];
                    d0 = ffma2(fA.x, acc, d0);
                    d1 = ffma2(fA.y, acc, d1);
                    d2 = ffma2(fB.x, acc, d2);
                    d3 = ffma2(fB.y, acc, d3);
                }
            }
        }
        // combine the two hidden halves across the thread pair
        d0 = fadd2(d0, __shfl_xor_sync(0xffffffffu, d0, 1));
        d1 = fadd2(d1, __shfl_xor_sync(0xffffffffu, d1, 1));
        d2 = fadd2(d2, __shfl_xor_sync(0xffffffffu, d2, 1));
        d3 = fadd2(d3, __shfl_xor_sync(0xffffffffu, d3, 1));

        float s0=0.f, s1=0.f, s2=0.f, s3=0.f;
        if (act){
            float l0,h0; unpack2(d0,l0,h0); s0 = l0 + h0;
            float l1,h1; unpack2(d1,l1,h1); s1 = l1 + h1;
            float l2,h2; unpack2(d2,l2,h2); s2 = l2 + h2;
            float l3,h3; unpack2(d3,l3,h3); s3 = l3 + h3;
            if (hh == 0){
                u32 dst = peer_pb + (u32)(((par*NPIX + p)) << 4);
                dsmem_st64(dst,     pack2(s0, s1));
                dsmem_st64(dst + 8, pack2(s2, s3));
                mbar_arrive_remote(peer_mb + (u32)(par << 3));
            }
        }
        // wait for peer partials (double-buffered phase)
        {
            u32 phase = par ? ph1 : ph0;
            mbar_wait(my_mb + (u32)(par << 3), phase);
            if (par) ph1 ^= 1u; else ph0 ^= 1u;
        }

        if (act){
            const ulonglong2 pr = *(const ulonglong2*)(pbuf + ((par*NPIX + p) << 1));
            float q0,q1; unpack2(pr.x,q0,q1);
            float q2,q3; unpack2(pr.y,q2,q3);
            float dl0 = (s0 + q0) + b2r0;
            float dl1 = (s1 + q1) + b2r1;
            float dl2 = (s2 + q2) + b2r2;
            float dl3 = (s3 + q3) + b2r3;
            x0 = y0  + dl0;
            x1 = y1v + dl1;
            x2 = y2v + dl2;
            x3 = scv + dl3;
            if (hh == 0) x0t[idx] = x0;
        }
        __syncthreads();                               // A: x0t ready

        float c0p = 0.f;
        if (act){
            float p00=x0t[idx-PP-1], p01=x0t[idx-PP], p02=x0t[idx-PP+1];
            float p10=x0t[idx-1],                      p12=x0t[idx+1];
            float p20=x0t[idx+PP-1], p21=x0t[idx+PP], p22=x0t[idx+PP+1];
            float pm = fmaxf(fmaxf(fmaxf(p00,p01), fmaxf(p02,p10)),
                             fmaxf(fmaxf(x0, p12), fmaxf(fmaxf(p20,p21), p22)));
            bool m = pre && (pm > 0.1f);
            c0p = m ? fminf(fmaxf(x0,   0.f),  1.f) : 0.f;
            float nc1 = m ? fminf(fmaxf(x1, -10.f), 10.f) : 0.f;
            float nc2 = m ? fminf(fmaxf(x2, -10.f), 10.f) : 0.f;
            float nc3 = m ? fminf(fmaxf(x3, -10.f), 10.f) : 0.f;
            same = (c0p == c0pPrev) && (nc1 == c1n) && (nc2 == c2n);
            c1n = nc1; c2n = nc2; c3n = nc3;
            if (hh == 0){
                sc0[idx] = c0p;
                s12[idx] = pack2(c1n, c2n);
                bitsv[p] = __float_as_uint(c0p);
            }
            c0pPrev = c0p; bitsPrev = __float_as_uint(c0p);
        }
        int nch = __syncthreads_count(!same);          // B: sc0/s12/bitsv ready

        if (tid >= 608){
            // selection warp: exact k-th-largest (redundant in both CTAs)
            u32 vals[10];
            #pragma unroll
            for (int j = 0; j < 10; j++) vals[j] = bitsv[lane + 32*j];
            const int need = (livW == 0) ? NPIX : livW;
            u32 nkth = 0u;
            int nliv;
            int pk = 0;
            #pragma unroll
            for (int j = 0; j < 10; j++){
                u32 v = vals[j];
                pk += (v >= 0x3F800000u) ? 1 : 0;
                pk += (v >= kthW)        ? 1024 : 0;
                pk += (v >= 0x3DCCCCCEu) ? (1<<20) : 0;
            }
            pk = __reduce_add_sync(0xffffffffu, pk);
            const int cone = pk & 1023, cold = (pk >> 10) & 1023, c01 = pk >> 20;
            if (need >= NPIX){
                nkth = 0u; nliv = c01;
            } else if (cone >= need){
                nkth = 0x3F800000u; nliv = cone;
            } else if (kthW != 0u && cold == need){
                nkth = kthW; nliv = (kthW > 0x3DCCCCCDu) ? need : c01;
            } else {
                u32 prefix = 0u; int cur = 0;
                #pragma unroll 1
                for (int r = 0; r < 15; r++){
                    u32 b1 = 1u << (29 - 2*r);
                    u32 tA = prefix | b1, tB = tA | (b1>>1), tC = prefix | (b1>>1);
                    int pc = 0;
                    #pragma unroll
                    for (int j = 0; j < 10; j++){
                        u32 v = vals[j];
                        pc += (v >= tA) ? 1 : 0;
                        pc += (v >= tB) ? 1024 : 0;
                        pc += (v >= tC) ? (1<<20) : 0;
                    }
                    pc = __reduce_add_sync(0xffffffffu, pc);
                    int cA = pc & 1023, cB = (pc >> 10) & 1023, cC = pc >> 20;
                    int chosen = -1;
                    if (cA >= need){
                        if (cB >= need){ prefix = tB; chosen = cB; }
                        else           { prefix = tA; chosen = cA; }
                    } else if (cC >= need){ prefix = tC; chosen = cC; }
                    if (chosen >= 0) cur = chosen;
                    if (chosen == need) break;
                }
                nkth = prefix;
                nliv = (prefix > 0x3DCCCCCDu) ? cur : c01;
            }
            kthW = nkth; livW = nliv;
            if (lane == 0){ *(u64*)sel = ((u64)(u32)nliv << 32) | (u64)nkth; }
        } else if (act){
            overlap_work(s12, sc0, idx, Y1,Y2,Y4,Y5,Y7,Y8, y1v,y2v, pn);
        }
        __syncthreads();                               // C: sel ready

        u64 nselv = *(const u64*)sel;
        bool fixp = (nch == 0) && (nselv == selv);     // identical in both CTAs
        selv = nselv;
        par ^= 1;
        if (fixp) break;                               // exact fixed point
    }

    // ---- outputs (rank 0 only): [cell | food | total | living] ----
    const u32 kthF = (u32)selv;
    const int livF = (int)(selv >> 32);
    float c0f = (act && bitsPrev >= kthF) ? c0pPrev : 0.f;

    if (rank == 0){
        if (act && hh == 0){
            int cb = (b*4)*NPIX + p;
            out[cb]           = c0f;
            out[cb +   NPIX]  = c1n;
            out[cb + 2*NPIX]  = c2n;
            out[cb + 3*NPIX]  = c3n;
            out[16*4*NPIX + b*NPIX + p] = food[b*NPIX + p];
        }
        float v = (act && hh == 0) ? c0f : 0.f;
        #pragma unroll
        for (int off = 16; off; off >>= 1) v += __shfl_down_sync(0xffffffffu, v, off);
        if ((tid & 31) == 0) wsum[tid >> 5] = v;
    }
    __syncthreads();
    if (rank == 0 && tid == 0){
        float t = 0.f;
        #pragma unroll
        for (int i = 0; i < 20; i++) t += wsum[i];
        out[23120 + b]      = t;
        out[23120 + 16 + b] = (float)livF;
    }
    CLUSTER_SYNC();   // no CTA exits while peer DSMEM traffic could be in flight
}

extern "C" void kernel_launch(void* const* d_in, const int* in_sizes, int n_in,
                              void* d_out, int out_size)
{
    const float* cell = (const float*)d_in[0];
    const float* food = (const float*)d_in[1];
    const float* fc1w = (const float*)d_in[3];
    const float* fc1b = (const float*)d_in[4];
    const float* fc2w = (const float*)d_in[5];
    const float* fc2b = (const float*)d_in[6];
    float* out = (float*)d_out;

    cudaFuncSetAttribute(ca_kernel, cudaFuncAttributeMaxDynamicSharedMemorySize, SMEM_BYTES);
    ca_kernel<<<32, NT, SMEM_BYTES>>>(cell, food, fc1w, fc1b, fc2w, fc2b, out);
}

// round 16
// speedup vs baseline: 1.1190x; 1.1190x over previous
#include <cuda_runtime.h>

#define NPIX   289
#define STEPS  512
#define PP     20           // padded tile pitch
#define TILE   384
#define NT     352          // 11 warps: 289 pixel threads + selection warp (tid>=320)

typedef unsigned long long u64;
typedef unsigned int u32;

__device__ __forceinline__ u64 ffma2(u64 a, u64 b, u64 c){
    u64 d; asm("fma.rn.f32x2 %0, %1, %2, %3;" : "=l"(d) : "l"(a), "l"(b), "l"(c)); return d;
}
__device__ __forceinline__ u64 pack2(float x, float y){
    u64 r; asm("mov.b64 %0, {%1, %2};" : "=l"(r)
               : "r"(__float_as_uint(x)), "r"(__float_as_uint(y)));
    return r;
}
__device__ __forceinline__ void unpack2(u64 v, float &x, float &y){
    u32 a, b; asm("mov.b64 {%0, %1}, %2;" : "=r"(a), "=r"(b) : "l"(v));
    x = __uint_as_float(a); y = __uint_as_float(b);
}
__device__ __forceinline__ int imax(int a, int b){ return a > b ? a : b; }
__device__ __forceinline__ u32 smem_addr_u32(const void* p){
    u32 a; asm("{ .reg .u64 t; cvta.to.shared.u64 t, %1; cvt.u32.u64 %0, t; }"
               : "=r"(a) : "l"(p));
    return a;
}
__device__ __forceinline__ void dsmem_st64(u32 addr, u64 v){
    asm volatile("st.shared::cluster.u64 [%0], %1;" :: "r"(addr), "l"(v) : "memory");
}
__device__ __forceinline__ void mbar_init(u32 addr, u32 cnt){
    asm volatile("mbarrier.init.shared.b64 [%0], %1;" :: "r"(addr), "r"(cnt) : "memory");
}
__device__ __forceinline__ void mbar_arrive_remote(u32 addr){
    asm volatile("mbarrier.arrive.release.cluster.shared::cluster.b64 _, [%0];"
                 :: "r"(addr) : "memory");
}
__device__ __forceinline__ void mbar_wait(u32 addr, u32 phase){
    asm volatile(
        "{\n\t"
        ".reg .pred P1;\n\t"
        "WAIT_%=:\n\t"
        "mbarrier.try_wait.parity.acquire.cluster.shared::cta.b64 P1, [%0], %1;\n\t"
        "@P1 bra.uni DONE_%=;\n\t"
        "bra.uni WAIT_%=;\n\t"
        "DONE_%=:\n\t"
        "}"
        :: "r"(addr), "r"(phase) : "memory");
}
#define CLUSTER_SYNC() do { \
    asm volatile("barrier.cluster.arrive.aligned;" ::: "memory"); \
    asm volatile("barrier.cluster.wait.aligned;"   ::: "memory"); \
} while(0)

/* u64 layout: w1I[32][10] | f2I[32][4] | s12[384] | pbuf[2][289][2] | mbar[2] */
#define OFF_W1I  0
#define OFF_F2I  320
#define OFF_S12  448
#define OFF_PBUF 832
#define OFF_MBAR (OFF_PBUF + 2*NPIX*2)
#define NU64     (OFF_MBAR + 2)
#define NF       (3*TILE + 12)                    /* sc0, x0t, sct, wsum */
#define NU32     (324)                            /* bitsv(320) + sel(4) */
#define SMEM_BYTES (NU64*8 + NF*4 + NU32*4)

// overlap work: ch1/ch2 packed stencil + ch0 neighbor prefetch
__device__ __forceinline__ void overlap_work(
    const u64* __restrict__ s12, const float* __restrict__ sc0, int idx,
    u64& Y1, u64& Y2, u64& Y4, u64& Y5, u64& Y7, u64& Y8,
    float& y1v, float& y2v, float* pn)
{
    u64 g00=s12[idx-PP-1], g01=s12[idx-PP], g02=s12[idx-PP+1];
    u64 g10=s12[idx-1],    g11=s12[idx],    g12=s12[idx+1];
    u64 g20=s12[idx+PP-1], g21=s12[idx+PP], g22=s12[idx+PP+1];
    float a00,c00; unpack2(g00,a00,c00);
    float a01,c01; unpack2(g01,a01,c01);
    float a02,c02; unpack2(g02,a02,c02);
    float a10,c10; unpack2(g10,a10,c10);
    float a11,c11; unpack2(g11,a11,c11);
    float a12,c12; unpack2(g12,a12,c12);
    float a20,c20; unpack2(g20,a20,c20);
    float a21,c21; unpack2(g21,a21,c21);
    float a22,c22; unpack2(g22,a22,c22);
    y1v = a11;  y2v = c11;
    float y4 = (a02 - a00 + 2.f*(a12 - a10) + a22 - a20) * 0.125f;
    float y7 = (a20 - a00 + 2.f*(a21 - a01) + a22 - a02) * 0.125f;
    float y5 = (c02 - c00 + 2.f*(c12 - c10) + c22 - c20) * 0.125f;
    float y8 = (c20 - c00 + 2.f*(c21 - c01) + c22 - c02) * 0.125f;
    Y1 = pack2(y1v,y1v); Y2 = pack2(y2v,y2v);
    Y4 = pack2(y4,y4);   Y5 = pack2(y5,y5);
    Y7 = pack2(y7,y7);   Y8 = pack2(y8,y8);
    pn[0]=sc0[idx-PP-1]; pn[1]=sc0[idx-PP]; pn[2]=sc0[idx-PP+1];
    pn[3]=sc0[idx-1];    pn[4]=sc0[idx+1];
    pn[5]=sc0[idx+PP-1]; pn[6]=sc0[idx+PP]; pn[7]=sc0[idx+PP+1];
}

__global__ void __launch_bounds__(NT, 1) __cluster_dims__(2, 1, 1) ca_kernel(
    const float* __restrict__ cell, const float* __restrict__ food,
    const float* __restrict__ fc1w, const float* __restrict__ fc1b,
    const float* __restrict__ fc2w, const float* __restrict__ fc2b,
    float* __restrict__ out)
{
    extern __shared__ u64 sm[];
    u64*   w1I  = sm + OFF_W1I;        // [32][10]
    u64*   f2I  = sm + OFF_F2I;        // [32][4]
    u64*   s12  = sm + OFF_S12;        // packed (c1,c2) tile
    u64*   pbuf = sm + OFF_PBUF;       // [2][NPIX][2] peer partial mailbox
    u64*   mbar = sm + OFF_MBAR;       // 2 mbarriers (double buffer)
    float* fb   = (float*)(sm + NU64);
    float* sc0  = fb;                  // unmasked c0p tile
    float* x0t  = fb + TILE;
    float* sct  = fb + 2*TILE;         // scent (prologue only)
    float* wsum = fb + 3*TILE;         // 12
    u32* bitsv  = (u32*)(wsum + 12);   // 320 (padded with zeros)
    u32* sel    = bitsv + 320;         // [0]=kth bits, [1]=living (read as u64)

    const int  tid  = threadIdx.x;
    const int  lane = tid & 31;
    u32 rank; asm("mov.u32 %0, %%cluster_ctarank;" : "=r"(rank));
    const int  b    = blockIdx.x >> 1;
    const int  p    = tid;
    const bool act  = tid < NPIX;
    const int  prow = p / 17, pcol = p % 17;
    const int  idx  = (prow + 1) * PP + (pcol + 1);

    for (int i = tid; i < TILE; i += NT){
        sc0[i]=0.f; x0t[i]=0.f; sct[i]=0.f; s12[i]=0ull;
    }
    if (tid < 320) bitsv[tid] = 0u;

    if (tid < 320){
        const int cjmap[9] = {0,1,2,4,5,6,8,9,10};
        int q = tid / 10, j = tid % 10;
        float wa = 0.f, wb = 0.f;
        if (j < 9){
            wa = fc1w[(2*q)   * 12 + cjmap[j]];
            wb = fc1w[(2*q+1) * 12 + cjmap[j]];
        }
        w1I[tid] = pack2(wa, wb);
    }
    if (tid < 128){
        int q = tid >> 2, o2 = tid & 3;
        f2I[tid] = pack2(fc2w[o2*64 + 2*q], fc2w[o2*64 + 2*q + 1]);
    }
    if (tid == 0){
        mbar_init(smem_addr_u32(mbar),     NPIX);
        mbar_init(smem_addr_u32(mbar + 1), NPIX);
    }
    const float b2r0 = fc2b[0], b2r1 = fc2b[1], b2r2 = fc2b[2], b2r3 = fc2b[3];
    __syncthreads();

    // ---- load cell, compute scent (constant). FULL state in BOTH CTAs ----
    float c0v = 0.f, scv = 0.f;
    if (act){
        c0v = cell[(b*4 + 0)*NPIX + p];
        float cv1 = cell[(b*4 + 1)*NPIX + p];
        float cv2 = cell[(b*4 + 2)*NPIX + p];
        sc0[idx] = c0v;
        s12[idx] = pack2(cv1, cv2);
        const float SW[5][5] = {
            {0.f,   0.125f,0.25f,0.125f,0.f  },
            {0.125f,0.25f, 0.5f, 0.25f, 0.125f},
            {0.25f, 0.5f,  1.0f, 0.5f,  0.25f },
            {0.125f,0.25f, 0.5f, 0.25f, 0.125f},
            {0.f,   0.125f,0.25f,0.125f,0.f  }};
        float s = 0.f;
        #pragma unroll
        for (int di = 0; di < 5; di++)
            #pragma unroll
            for (int dj = 0; dj < 5; dj++){
                int rr2 = prow + di - 2, c2 = pcol + dj - 2;
                if (rr2 >= 0 && rr2 < 17 && c2 >= 0 && c2 < 17)
                    s += SW[di][dj] * food[b*NPIX + rr2*17 + c2];
            }
        scv = s;
        sct[idx] = s;
    }
    int living0 = __syncthreads_count(act && (c0v > 0.1f));
    if (tid == 0){ *(u64*)sel = ((u64)(u32)living0 << 32); }
    u32 kthW = 0u;
    int livW = living0;
    u64 selv = ((u64)(u32)living0 << 32);

    // ---- hbias fold into REGISTERS (own 16 pairs: q = rank*16 + t) ----
    u64 hbR[16];
    if (act){
        float m00=sct[idx-PP-1], m01=sct[idx-PP], m02=sct[idx-PP+1];
        float m10=sct[idx-1],                     m12=sct[idx+1];
        float m20=sct[idx+PP-1], m21=sct[idx+PP], m22=sct[idx+PP+1];
        float dsx = (m02 - m00 + 2.f*(m12 - m10) + m22 - m20) * 0.125f;
        float dsy = (m20 - m00 + 2.f*(m21 - m01) + m22 - m02) * 0.125f;
        #pragma unroll
        for (int t = 0; t < 16; t++){
            int q = (int)(rank << 4) + t;
            float h0 = fc1b[2*q]   + fc1w[(2*q)*12+3]  *scv
                     + fc1w[(2*q)*12+7]  *dsx + fc1w[(2*q)*12+11]  *dsy;
            float h1 = fc1b[2*q+1] + fc1w[(2*q+1)*12+3]*scv
                     + fc1w[(2*q+1)*12+7]*dsx + fc1w[(2*q+1)*12+11]*dsy;
            hbR[t] = pack2(h0, h1);
        }
    } else {
        #pragma unroll
        for (int t = 0; t < 16; t++) hbR[t] = 0ull;
    }

    // ---- DSMEM addressing ----
    const u32 my_pb = smem_addr_u32(pbuf);
    const u32 my_mb = smem_addr_u32(mbar);
    u32 peer_pb, peer_mb;
    asm("mapa.shared::cluster.u32 %0, %1, %2;" : "=r"(peer_pb) : "r"(my_pb), "r"(rank ^ 1u));
    asm("mapa.shared::cluster.u32 %0, %1, %2;" : "=r"(peer_mb) : "r"(my_mb), "r"(rank ^ 1u));

    // peer mbarriers initialized before any cross-CTA store/arrive
    CLUSTER_SYNC();

    // ---- prologue overlap ----
    u64 Y1=0,Y2=0,Y4=0,Y5=0,Y7=0,Y8=0;
    float y1v=0.f, y2v=0.f;
    float pn[8] = {0,0,0,0,0,0,0,0};
    if (act) overlap_work(s12, sc0, idx, Y1,Y2,Y4,Y5,Y7,Y8, y1v,y2v, pn);

    float c0pPrev = c0v;
    u32   bitsPrev = __float_as_uint(c0v);
    float c1n = 0.f, c2n = 0.f, c3n = 0.f;
    int par = 0;
    u32 ph0 = 0, ph1 = 0;

    for (int st = 0; st < STEPS; st++){
        const u32 kth = (u32)selv;

        float x0=0.f, x1=0.f, x2=0.f, x3=0.f;
        bool  pre = false;
        u64 d0=0ull, d1=0ull, d2=0ull, d3=0ull;
        float y0 = 0.f;
        float s0=0.f, s1=0.f, s2=0.f, s3=0.f;
        bool same = true;

        if (act){
            // apply mask to prefetched ch0 neighbors (pure ALU)
            u32 mb[8]; float n[8];
            #pragma unroll
            for (int i = 0; i < 8; i++){
                u32 q = __float_as_uint(pn[i]);
                mb[i] = (q >= kth) ? q : 0u;
                n[i]  = __uint_as_float(mb[i]);
            }
            u32 mc = (bitsPrev >= kth) ? bitsPrev : 0u;
            y0 = __uint_as_float(mc);
            int mi = imax(imax(imax((int)mb[0],(int)mb[1]), imax((int)mb[2],(int)mb[3])),
                          imax(imax((int)mb[4],(int)mb[5]), imax(imax((int)mb[6],(int)mb[7]),(int)mc)));
            pre = mi > 0x3DCCCCCD;   // > 0.1f
            float y3 = (n[2] - n[0] + 2.f*(n[4] - n[3]) + n[7] - n[5]) * 0.125f;
            float y6 = (n[5] - n[0] + 2.f*(n[6] - n[1]) + n[7] - n[2]) * 0.125f;

            u64 Y0=pack2(y0,y0), Y3=pack2(y3,y3), Y6=pack2(y6,y6);

            // MLP over OWN 16 hidden pairs (warp-uniform weight rows)
            #pragma unroll
            for (int t = 0; t < 16; t++){
                const int q = (int)(rank << 4) + t;
                u64 acc = hbR[t];
                const ulonglong2* wr = reinterpret_cast<const ulonglong2*>(w1I + q*10);
                ulonglong2 wA = wr[0], wB = wr[1], wC = wr[2], wD = wr[3], wE = wr[4];
                acc = ffma2(wA.x, Y0, acc);
                acc = ffma2(wA.y, Y1, acc);
                acc = ffma2(wB.x, Y2, acc);
                acc = ffma2(wB.y, Y3, acc);
                acc = ffma2(wC.x, Y4, acc);
                acc = ffma2(wC.y, Y5, acc);
                acc = ffma2(wD.x, Y6, acc);
                acc = ffma2(wD.y, Y7, acc);
                acc = ffma2(wE.x, Y8, acc);
                // relu via signed-int max on packed halves (ALU pipe)
                float lo, hi; unpack2(acc, lo, hi);
                int li  = imax((int)__float_as_uint(lo), 0);
                int hi2 = imax((int)__float_as_uint(hi), 0);
                acc = pack2(__uint_as_float((u32)li), __uint_as_float((u32)hi2));
                const ulonglong2* fr = reinterpret_cast<const ulonglong2*>(f2I + q*4);
                ulonglong2 fA = fr[0], fB = fr[1];
                d0 = ffma2(fA.x, acc, d0);
                d1 = ffma2(fA.y, acc, d1);
                d2 = ffma2(fB.x, acc, d2);
                d3 = ffma2(fB.y, acc, d3);
            }
            // own partial sums (lo+hi), send to peer mailbox + arrive
            float l0,h0; unpack2(d0,l0,h0); s0 = l0 + h0;
            float l1,h1; unpack2(d1,l1,h1); s1 = l1 + h1;
            float l2,h2; unpack2(d2,l2,h2); s2 = l2 + h2;
            float l3,h3; unpack2(d3,l3,h3); s3 = l3 + h3;
            u32 dst = peer_pb + (u32)(((par*NPIX + p)) << 4);
            dsmem_st64(dst,     pack2(s0, s1));
            dsmem_st64(dst + 8, pack2(s2, s3));
            mbar_arrive_remote(peer_mb + (u32)(par << 3));
        }
        // wait for peer partials (act threads only; barrier A orders the rest)
        if (act){
            u32 phase = par ? ph1 : ph0;
            mbar_wait(my_mb + (u32)(par << 3), phase);
        }
        if (par) ph1 ^= 1u; else ph0 ^= 1u;

        if (act){
            const ulonglong2 pr = *(const ulonglong2*)(pbuf + ((par*NPIX + p) << 1));
            float q0,q1; unpack2(pr.x,q0,q1);
            float q2,q3; unpack2(pr.y,q2,q3);
            float dl0 = (s0 + q0) + b2r0;
            float dl1 = (s1 + q1) + b2r1;
            float dl2 = (s2 + q2) + b2r2;
            float dl3 = (s3 + q3) + b2r3;
            x0 = y0  + dl0;
            x1 = y1v + dl1;
            x2 = y2v + dl2;
            x3 = scv + dl3;
            x0t[idx] = x0;
        }
        __syncthreads();                               // A: x0t ready

        float c0p = 0.f;
        if (act){
            float p00=x0t[idx-PP-1], p01=x0t[idx-PP], p02=x0t[idx-PP+1];
            float p10=x0t[idx-1],                      p12=x0t[idx+1];
            float p20=x0t[idx+PP-1], p21=x0t[idx+PP], p22=x0t[idx+PP+1];
            float pm = fmaxf(fmaxf(fmaxf(p00,p01), fmaxf(p02,p10)),
                             fmaxf(fmaxf(x0, p12), fmaxf(fmaxf(p20,p21), p22)));
            bool m = pre && (pm > 0.1f);
            c0p = m ? fminf(fmaxf(x0,   0.f),  1.f) : 0.f;
            float nc1 = m ? fminf(fmaxf(x1, -10.f), 10.f) : 0.f;
            float nc2 = m ? fminf(fmaxf(x2, -10.f), 10.f) : 0.f;
            float nc3 = m ? fminf(fmaxf(x3, -10.f), 10.f) : 0.f;
            same = (c0p == c0pPrev) && (nc1 == c1n) && (nc2 == c2n);
            c1n = nc1; c2n = nc2; c3n = nc3;
            sc0[idx] = c0p;
            s12[idx] = pack2(c1n, c2n);
            bitsv[p] = __float_as_uint(c0p);
            c0pPrev = c0p; bitsPrev = __float_as_uint(c0p);
        }
        int nch = __syncthreads_count(!same);          // B: sc0/s12/bitsv ready

        if (tid >= 320){
            // selection warp: exact k-th-largest (redundant in both CTAs)
            u32 vals[10];
            #pragma unroll
            for (int j = 0; j < 10; j++) vals[j] = bitsv[lane + 32*j];
            const int need = (livW == 0) ? NPIX : livW;
            u32 nkth = 0u;
            int nliv;
            int pk = 0;
            #pragma unroll
            for (int j = 0; j < 10; j++){
                u32 v = vals[j];
                pk += (v >= 0x3F800000u) ? 1 : 0;
                pk += (v >= kthW)        ? 1024 : 0;
                pk += (v >= 0x3DCCCCCEu) ? (1<<20) : 0;
            }
            pk = __reduce_add_sync(0xffffffffu, pk);
            const int cone = pk & 1023, cold = (pk >> 10) & 1023, c01 = pk >> 20;
            if (need >= NPIX){
                nkth = 0u; nliv = c01;
            } else if (cone >= need){
                nkth = 0x3F800000u; nliv = cone;
            } else if (kthW != 0u && cold == need){
                nkth = kthW; nliv = (kthW > 0x3DCCCCCDu) ? need : c01;
            } else {
                u32 prefix = 0u; int cur = 0;
                #pragma unroll 1
                for (int r = 0; r < 15; r++){
                    u32 b1 = 1u << (29 - 2*r);
                    u32 tA = prefix | b1, tB = tA | (b1>>1), tC = prefix | (b1>>1);
                    int pc = 0;
                    #pragma unroll
                    for (int j = 0; j < 10; j++){
                        u32 v = vals[j];
                        pc += (v >= tA) ? 1 : 0;
                        pc += (v >= tB) ? 1024 : 0;
                        pc += (v >= tC) ? (1<<20) : 0;
                    }
                    pc = __reduce_add_sync(0xffffffffu, pc);
                    int cA = pc & 1023, cB = (pc >> 10) & 1023, cC = pc >> 20;
                    int chosen = -1;
                    if (cA >= need){
                        if (cB >= need){ prefix = tB; chosen = cB; }
                        else           { prefix = tA; chosen = cA; }
                    } else if (cC >= need){ prefix = tC; chosen = cC; }
                    if (chosen >= 0) cur = chosen;
                    if (chosen == need) break;
                }
                nkth = prefix;
                nliv = (prefix > 0x3DCCCCCDu) ? cur : c01;
            }
            kthW = nkth; livW = nliv;
            if (lane == 0){ *(u64*)sel = ((u64)(u32)nliv << 32) | (u64)nkth; }
        } else if (act){
            overlap_work(s12, sc0, idx, Y1,Y2,Y4,Y5,Y7,Y8, y1v,y2v, pn);
        }
        __syncthreads();                               // C: sel ready

        u64 nselv = *(const u64*)sel;
        bool fixp = (nch == 0) && (nselv == selv);     // identical in both CTAs
        selv = nselv;
        par ^= 1;
        if (fixp) break;                               // exact fixed point
    }

    // ---- outputs (rank 0 only): [cell | food | total | living] ----
    const u32 kthF = (u32)selv;
    const int livF = (int)(selv >> 32);
    float c0f = (act && bitsPrev >= kthF) ? c0pPrev : 0.f;

    if (rank == 0){
        if (act){
            int cb = (b*4)*NPIX + p;
            out[cb]           = c0f;
            out[cb +   NPIX]  = c1n;
            out[cb + 2*NPIX]  = c2n;
            out[cb + 3*NPIX]  = c3n;
            out[16*4*NPIX + b*NPIX + p] = food[b*NPIX + p];
        }
        float v = act ? c0f : 0.f;
        #pragma unroll
        for (int off = 16; off; off >>= 1) v += __shfl_down_sync(0xffffffffu, v, off);
        if ((tid & 31) == 0) wsum[tid >> 5] = v;
    }
    __syncthreads();
    if (rank == 0 && tid == 0){
        float t = 0.f;
        #pragma unroll
        for (int i = 0; i < 11; i++) t += wsum[i];
        out[23120 + b]      = t;
        out[23120 + 16 + b] = (float)livF;
    }
    CLUSTER_SYNC();   // no CTA exits while peer DSMEM traffic could be in flight
}

extern "C" void kernel_launch(void* const* d_in, const int* in_sizes, int n_in,
                              void* d_out, int out_size)
{
    const float* cell = (const float*)d_in[0];
    const float* food = (const float*)d_in[1];
    const float* fc1w = (const float*)d_in[3];
    const float* fc1b = (const float*)d_in[4];
    const float* fc2w = (const float*)d_in[5];
    const float* fc2b = (const float*)d_in[6];
    float* out = (float*)d_out;

    cudaFuncSetAttribute(ca_kernel, cudaFuncAttributeMaxDynamicSharedMemorySize, SMEM_BYTES);
    ca_kernel<<<32, NT, SMEM_BYTES>>>(cell, food, fc1w, fc1b, fc2w, fc2b, out);
}

// round 17
// speedup vs baseline: 1.1699x; 1.0455x over previous
#include <cuda_runtime.h>

#define NPIX   289
#define STEPS  512
#define PP     20           // padded tile pitch
#define TILE   384
#define NT     352          // 11 warps: 289 pixel threads + selection warp (tid>=320)
#define HBPS   18           // hbias per-pixel row stride (u64) = 144B, conflict-free

typedef unsigned long long u64;
typedef unsigned int u32;

__device__ __forceinline__ u64 ffma2(u64 a, u64 b, u64 c){
    u64 d; asm("fma.rn.f32x2 %0, %1, %2, %3;" : "=l"(d) : "l"(a), "l"(b), "l"(c)); return d;
}
__device__ __forceinline__ u64 pack2(float x, float y){
    u64 r; asm("mov.b64 %0, {%1, %2};" : "=l"(r)
               : "r"(__float_as_uint(x)), "r"(__float_as_uint(y)));
    return r;
}
__device__ __forceinline__ void unpack2(u64 v, float &x, float &y){
    u32 a, b; asm("mov.b64 {%0, %1}, %2;" : "=r"(a), "=r"(b) : "l"(v));
    x = __uint_as_float(a); y = __uint_as_float(b);
}
__device__ __forceinline__ int imax(int a, int b){ return a > b ? a : b; }
__device__ __forceinline__ u32 smem_addr_u32(const void* p){
    u32 a; asm("{ .reg .u64 t; cvta.to.shared.u64 t, %1; cvt.u32.u64 %0, t; }"
               : "=r"(a) : "l"(p));
    return a;
}
__device__ __forceinline__ void dsmem_st64(u32 addr, u64 v){
    asm volatile("st.shared::cluster.u64 [%0], %1;" :: "r"(addr), "l"(v) : "memory");
}
#define CLUSTER_SYNC() do { \
    asm volatile("barrier.cluster.arrive.aligned;" ::: "memory"); \
    asm volatile("barrier.cluster.wait.aligned;"   ::: "memory"); \
} while(0)

/* u64 layout: w1A[32][6] | w1B[32][4] | f2I[32][4] | s12[384] | pbuf[2][289][2] | hbr[289][18] */
#define OFF_W1A  0
#define OFF_W1B  (OFF_W1A + 192)
#define OFF_F2I  (OFF_W1B + 128)
#define OFF_S12  (OFF_F2I + 128)
#define OFF_PBUF (OFF_S12 + TILE)
#define OFF_HBR  (OFF_PBUF + 2*NPIX*2)
#define NU64     (OFF_HBR + NPIX*HBPS)
#define NF       (3*TILE + 12)                    /* sc0, x0t, sct, wsum */
#define NU32     (324)                            /* bitsv(320) + sel(4) */
#define SMEM_BYTES (NU64*8 + NF*4 + NU32*4)

// overlap work (kth-independent): ch1/ch2 packed stencil -> 6-term MLP partials
// into REGISTER pacc[16] (hbias loaded from smem row), + ch0 neighbor prefetch.
__device__ __forceinline__ void overlap_work(
    const u64* __restrict__ s12, const float* __restrict__ sc0,
    const u64* __restrict__ w1A, const u64* __restrict__ hbrow, int rank16,
    int idx, u64* pacc, float& y1v, float& y2v, float* pn)
{
    u64 g00=s12[idx-PP-1], g01=s12[idx-PP], g02=s12[idx-PP+1];
    u64 g10=s12[idx-1],    g11=s12[idx],    g12=s12[idx+1];
    u64 g20=s12[idx+PP-1], g21=s12[idx+PP], g22=s12[idx+PP+1];
    float a00,c00; unpack2(g00,a00,c00);
    float a01,c01; unpack2(g01,a01,c01);
    float a02,c02; unpack2(g02,a02,c02);
    float a10,c10; unpack2(g10,a10,c10);
    float a11,c11; unpack2(g11,a11,c11);
    float a12,c12; unpack2(g12,a12,c12);
    float a20,c20; unpack2(g20,a20,c20);
    float a21,c21; unpack2(g21,a21,c21);
    float a22,c22; unpack2(g22,a22,c22);
    y1v = a11;  y2v = c11;
    float y4 = (a02 - a00 + 2.f*(a12 - a10) + a22 - a20) * 0.125f;
    float y7 = (a20 - a00 + 2.f*(a21 - a01) + a22 - a02) * 0.125f;
    float y5 = (c02 - c00 + 2.f*(c12 - c10) + c22 - c20) * 0.125f;
    float y8 = (c20 - c00 + 2.f*(c21 - c01) + c22 - c02) * 0.125f;
    u64 Y1 = pack2(y1v,y1v), Y2 = pack2(y2v,y2v);
    u64 Y4 = pack2(y4,y4),   Y5 = pack2(y5,y5);
    u64 Y7 = pack2(y7,y7),   Y8 = pack2(y8,y8);

    #pragma unroll
    for (int t2 = 0; t2 < 8; t2++){
        ulonglong2 hbp = *(const ulonglong2*)(hbrow + 2*t2);
        #pragma unroll
        for (int tt = 0; tt < 2; tt++){
            const int t = 2*t2 + tt;
            const int q = rank16 + t;
            u64 acc = tt ? hbp.y : hbp.x;
            const ulonglong2* wr = reinterpret_cast<const ulonglong2*>(w1A + q*6);
            ulonglong2 wA = wr[0], wB = wr[1], wC = wr[2];
            acc = ffma2(wA.x, Y1, acc);
            acc = ffma2(wA.y, Y2, acc);
            acc = ffma2(wB.x, Y4, acc);
            acc = ffma2(wB.y, Y5, acc);
            acc = ffma2(wC.x, Y7, acc);
            acc = ffma2(wC.y, Y8, acc);
            pacc[t] = acc;
        }
    }

    pn[0]=sc0[idx-PP-1]; pn[1]=sc0[idx-PP]; pn[2]=sc0[idx-PP+1];
    pn[3]=sc0[idx-1];    pn[4]=sc0[idx+1];
    pn[5]=sc0[idx+PP-1]; pn[6]=sc0[idx+PP]; pn[7]=sc0[idx+PP+1];
}

__global__ void __launch_bounds__(NT, 1) __cluster_dims__(2, 1, 1) ca_kernel(
    const float* __restrict__ cell, const float* __restrict__ food,
    const float* __restrict__ fc1w, const float* __restrict__ fc1b,
    const float* __restrict__ fc2w, const float* __restrict__ fc2b,
    float* __restrict__ out)
{
    extern __shared__ u64 sm[];
    u64*   w1A  = sm + OFF_W1A;        // [32][6]  (y1,y2,y4,y5,y7,y8)
    u64*   w1B  = sm + OFF_W1B;        // [32][4]  (y0,y3,y6,pad)
    u64*   f2I  = sm + OFF_F2I;        // [32][4]
    u64*   s12  = sm + OFF_S12;        // packed (c1,c2) tile
    u64*   pbuf = sm + OFF_PBUF;       // [2][NPIX][2] peer partial mailbox
    u64*   hbr  = sm + OFF_HBR;        // [NPIX][HBPS] hbias rows
    float* fb   = (float*)(sm + NU64);
    float* sc0  = fb;                  // unmasked c0p tile
    float* x0t  = fb + TILE;
    float* sct  = fb + 2*TILE;         // scent (prologue only)
    float* wsum = fb + 3*TILE;         // 12
    u32* bitsv  = (u32*)(wsum + 12);   // 320 (padded with zeros)
    u32* sel    = bitsv + 320;         // [0]=kth bits, [1]=living (read as u64)

    const int  tid  = threadIdx.x;
    const int  lane = tid & 31;
    u32 rank; asm("mov.u32 %0, %%cluster_ctarank;" : "=r"(rank));
    const int  rank16 = (int)(rank << 4);
    const int  b    = blockIdx.x >> 1;
    const int  p    = tid;
    const bool act  = tid < NPIX;
    const int  prow = p / 17, pcol = p % 17;
    const int  idx  = (prow + 1) * PP + (pcol + 1);
    const u64* hbrow = hbr + p * HBPS;

    for (int i = tid; i < TILE; i += NT){
        sc0[i]=0.f; x0t[i]=0.f; sct[i]=0.f; s12[i]=0ull;
    }
    if (tid < 320) bitsv[tid] = 0u;

    // ---- weight interleave ----
    if (tid < 192){
        const int cjA[6] = {1,2,5,6,9,10};
        int q = tid / 6, j = tid % 6;
        w1A[tid] = pack2(fc1w[(2*q)*12 + cjA[j]], fc1w[(2*q+1)*12 + cjA[j]]);
    }
    if (tid < 128){
        const int cjB[4] = {0,4,8,0};
        int q = tid >> 2, j = tid & 3;
        float wa = 0.f, wb = 0.f;
        if (j < 3){
            wa = fc1w[(2*q)*12 + cjB[j]];
            wb = fc1w[(2*q+1)*12 + cjB[j]];
        }
        w1B[tid] = pack2(wa, wb);
    }
    if (tid >= 192 && tid < 320){
        int t2 = tid - 192;
        int q = t2 >> 2, o2 = t2 & 3;
        f2I[t2] = pack2(fc2w[o2*64 + 2*q], fc2w[o2*64 + 2*q + 1]);
    }
    const float b2r0 = fc2b[0], b2r1 = fc2b[1], b2r2 = fc2b[2], b2r3 = fc2b[3];
    __syncthreads();

    // ---- load cell, compute scent (constant). FULL state in BOTH CTAs ----
    float c0v = 0.f, scv = 0.f;
    if (act){
        c0v = cell[(b*4 + 0)*NPIX + p];
        float cv1 = cell[(b*4 + 1)*NPIX + p];
        float cv2 = cell[(b*4 + 2)*NPIX + p];
        sc0[idx] = c0v;
        s12[idx] = pack2(cv1, cv2);
        const float SW[5][5] = {
            {0.f,   0.125f,0.25f,0.125f,0.f  },
            {0.125f,0.25f, 0.5f, 0.25f, 0.125f},
            {0.25f, 0.5f,  1.0f, 0.5f,  0.25f },
            {0.125f,0.25f, 0.5f, 0.25f, 0.125f},
            {0.f,   0.125f,0.25f,0.125f,0.f  }};
        float s = 0.f;
        #pragma unroll
        for (int di = 0; di < 5; di++)
            #pragma unroll
            for (int dj = 0; dj < 5; dj++){
                int rr2 = prow + di - 2, c2 = pcol + dj - 2;
                if (rr2 >= 0 && rr2 < 17 && c2 >= 0 && c2 < 17)
                    s += SW[di][dj] * food[b*NPIX + rr2*17 + c2];
            }
        scv = s;
        sct[idx] = s;
    }
    int living0 = __syncthreads_count(act && (c0v > 0.1f));
    if (tid == 0){ *(u64*)sel = ((u64)(u32)living0 << 32); }
    u32 kthW = 0u;
    int livW = living0;
    u64 selv = ((u64)(u32)living0 << 32);

    // ---- hbias fold -> smem rows (own rank's 16 pairs) ----
    if (act){
        float m00=sct[idx-PP-1], m01=sct[idx-PP], m02=sct[idx-PP+1];
        float m10=sct[idx-1],                     m12=sct[idx+1];
        float m20=sct[idx+PP-1], m21=sct[idx+PP], m22=sct[idx+PP+1];
        float dsx = (m02 - m00 + 2.f*(m12 - m10) + m22 - m20) * 0.125f;
        float dsy = (m20 - m00 + 2.f*(m21 - m01) + m22 - m02) * 0.125f;
        #pragma unroll
        for (int t = 0; t < 16; t++){
            int q = rank16 + t;
            float h0 = fc1b[2*q]   + fc1w[(2*q)*12+3]  *scv
                     + fc1w[(2*q)*12+7]  *dsx + fc1w[(2*q)*12+11]  *dsy;
            float h1 = fc1b[2*q+1] + fc1w[(2*q+1)*12+3]*scv
                     + fc1w[(2*q+1)*12+7]*dsx + fc1w[(2*q+1)*12+11]*dsy;
            ((u64*)hbrow)[t] = pack2(h0, h1);
        }
    }
    __syncthreads();

    // ---- DSMEM addressing ----
    const u32 my_pb = smem_addr_u32(pbuf);
    u32 peer_pb;
    asm("mapa.shared::cluster.u32 %0, %1, %2;" : "=r"(peer_pb) : "r"(my_pb), "r"(rank ^ 1u));

    // peer fully initialized before first cross-CTA store
    CLUSTER_SYNC();

    // ---- prologue overlap: pacc + prefetch for step 0 ----
    u64 pacc[16];
    #pragma unroll
    for (int t = 0; t < 16; t++) pacc[t] = 0ull;
    float y1v=0.f, y2v=0.f;
    float pn[8] = {0,0,0,0,0,0,0,0};
    if (act) overlap_work(s12, sc0, w1A, hbrow, rank16, idx, pacc, y1v, y2v, pn);

    float c0pPrev = c0v;
    u32   bitsPrev = __float_as_uint(c0v);
    float c1n = 0.f, c2n = 0.f, c3n = 0.f;
    int par = 0;

    for (int st = 0; st < STEPS; st++){
        const u32 kth = (u32)selv;

        float x0=0.f, x1=0.f, x2=0.f, x3=0.f;
        bool  pre = false;
        u64 d0=0ull, d1=0ull, d2=0ull, d3=0ull;
        float y0 = 0.f;
        float s0=0.f, s1=0.f, s2=0.f, s3=0.f;
        bool same = true;

        if (act){
            // apply mask to prefetched ch0 neighbors (pure ALU)
            u32 mb[8]; float n[8];
            #pragma unroll
            for (int i = 0; i < 8; i++){
                u32 q = __float_as_uint(pn[i]);
                mb[i] = (q >= kth) ? q : 0u;
                n[i]  = __uint_as_float(mb[i]);
            }
            u32 mc = (bitsPrev >= kth) ? bitsPrev : 0u;
            y0 = __uint_as_float(mc);
            int mi = imax(imax(imax((int)mb[0],(int)mb[1]), imax((int)mb[2],(int)mb[3])),
                          imax(imax((int)mb[4],(int)mb[5]), imax(imax((int)mb[6],(int)mb[7]),(int)mc)));
            pre = mi > 0x3DCCCCCD;   // > 0.1f
            float y3 = (n[2] - n[0] + 2.f*(n[4] - n[3]) + n[7] - n[5]) * 0.125f;
            float y6 = (n[5] - n[0] + 2.f*(n[6] - n[1]) + n[7] - n[2]) * 0.125f;

            u64 Y0=pack2(y0,y0), Y3=pack2(y3,y3), Y6=pack2(y6,y6);

            // finish MLP: pacc + w0*Y0 + w3*Y3 + w6*Y6, relu, fc2
            #pragma unroll
            for (int t = 0; t < 16; t++){
                const int q = rank16 + t;
                u64 acc = pacc[t];
                const ulonglong2* wb = reinterpret_cast<const ulonglong2*>(w1B + q*4);
                ulonglong2 w03 = wb[0], w6p = wb[1];
                acc = ffma2(w03.x, Y0, acc);
                acc = ffma2(w03.y, Y3, acc);
                acc = ffma2(w6p.x, Y6, acc);
                // relu via signed-int max on packed halves (ALU pipe)
                float lo, hi; unpack2(acc, lo, hi);
                int li  = imax((int)__float_as_uint(lo), 0);
                int hi2 = imax((int)__float_as_uint(hi), 0);
                acc = pack2(__uint_as_float((u32)li), __uint_as_float((u32)hi2));
                const ulonglong2* fr = reinterpret_cast<const ulonglong2*>(f2I + q*4);
                ulonglong2 fA = fr[0], fB = fr[1];
                d0 = ffma2(fA.x, acc, d0);
                d1 = ffma2(fA.y, acc, d1);
                d2 = ffma2(fB.x, acc, d2);
                d3 = ffma2(fB.y, acc, d3);
            }
            // own partial sums (lo+hi), send to peer mailbox
            float l0,h0; unpack2(d0,l0,h0); s0 = l0 + h0;
            float l1,h1; unpack2(d1,l1,h1); s1 = l1 + h1;
            float l2,h2; unpack2(d2,l2,h2); s2 = l2 + h2;
            float l3,h3; unpack2(d3,l3,h3); s3 = l3 + h3;
            u32 dst = peer_pb + (u32)(((par*NPIX + p)) << 4);
            dsmem_st64(dst,     pack2(s0, s1));
            dsmem_st64(dst + 8, pack2(s2, s3));
        }
        CLUSTER_SYNC();                                // peer partials delivered

        if (act){
            const ulonglong2 pr = *(const ulonglong2*)(pbuf + ((par*NPIX + p) << 1));
            float q0,q1; unpack2(pr.x,q0,q1);
            float q2,q3; unpack2(pr.y,q2,q3);
            float dl0 = (s0 + q0) + b2r0;
            float dl1 = (s1 + q1) + b2r1;
            float dl2 = (s2 + q2) + b2r2;
            float dl3 = (s3 + q3) + b2r3;
            x0 = y0  + dl0;
            x1 = y1v + dl1;
            x2 = y2v + dl2;
            x3 = scv + dl3;
            x0t[idx] = x0;
        }
        __syncthreads();                               // A: x0t ready

        float c0p = 0.f;
        if (act){
            float p00=x0t[idx-PP-1], p01=x0t[idx-PP], p02=x0t[idx-PP+1];
            float p10=x0t[idx-1],                      p12=x0t[idx+1];
            float p20=x0t[idx+PP-1], p21=x0t[idx+PP], p22=x0t[idx+PP+1];
            float pm = fmaxf(fmaxf(fmaxf(p00,p01), fmaxf(p02,p10)),
                             fmaxf(fmaxf(x0, p12), fmaxf(fmaxf(p20,p21), p22)));
            bool m = pre && (pm > 0.1f);
            c0p = m ? fminf(fmaxf(x0,   0.f),  1.f) : 0.f;
            float nc1 = m ? fminf(fmaxf(x1, -10.f), 10.f) : 0.f;
            float nc2 = m ? fminf(fmaxf(x2, -10.f), 10.f) : 0.f;
            float nc3 = m ? fminf(fmaxf(x3, -10.f), 10.f) : 0.f;
            same = (c0p == c0pPrev) && (nc1 == c1n) && (nc2 == c2n);
            c1n = nc1; c2n = nc2; c3n = nc3;
            sc0[idx] = c0p;
            s12[idx] = pack2(c1n, c2n);
            bitsv[p] = __float_as_uint(c0p);
            c0pPrev = c0p; bitsPrev = __float_as_uint(c0p);
        }
        int nch = __syncthreads_count(!same);          // B: sc0/s12/bitsv ready

        if (tid >= 320){
            // selection warp: exact k-th-largest (redundant in both CTAs)
            u32 vals[10];
            #pragma unroll
            for (int j = 0; j < 10; j++) vals[j] = bitsv[lane + 32*j];
            const int need = (livW == 0) ? NPIX : livW;
            u32 nkth = 0u;
            int nliv;
            int pk = 0;
            #pragma unroll
            for (int j = 0; j < 10; j++){
                u32 v = vals[j];
                pk += (v >= 0x3F800000u) ? 1 : 0;
                pk += (v >= kthW)        ? 1024 : 0;
                pk += (v >= 0x3DCCCCCEu) ? (1<<20) : 0;
            }
            pk = __reduce_add_sync(0xffffffffu, pk);
            const int cone = pk & 1023, cold = (pk >> 10) & 1023, c01 = pk >> 20;
            if (need >= NPIX){
                nkth = 0u; nliv = c01;
            } else if (cone >= need){
                nkth = 0x3F800000u; nliv = cone;
            } else if (kthW != 0u && cold == need){
                nkth = kthW; nliv = (kthW > 0x3DCCCCCDu) ? need : c01;
            } else {
                u32 prefix = 0u; int cur = 0;
                #pragma unroll 1
                for (int r = 0; r < 15; r++){
                    u32 b1 = 1u << (29 - 2*r);
                    u32 tA = prefix | b1, tB = tA | (b1>>1), tC = prefix | (b1>>1);
                    int pc = 0;
                    #pragma unroll
                    for (int j = 0; j < 10; j++){
                        u32 v = vals[j];
                        pc += (v >= tA) ? 1 : 0;
                        pc += (v >= tB) ? 1024 : 0;
                        pc += (v >= tC) ? (1<<20) : 0;
                    }
                    pc = __reduce_add_sync(0xffffffffu, pc);
                    int cA = pc & 1023, cB = (pc >> 10) & 1023, cC = pc >> 20;
                    int chosen = -1;
                    if (cA >= need){
                        if (cB >= need){ prefix = tB; chosen = cB; }
                        else           { prefix = tA; chosen = cA; }
                    } else if (cC >= need){ prefix = tC; chosen = cC; }
                    if (chosen >= 0) cur = chosen;
                    if (chosen == need) break;
                }
                nkth = prefix;
                nliv = (prefix > 0x3DCCCCCDu) ? cur : c01;
            }
            kthW = nkth; livW = nliv;
            if (lane == 0){ *(u64*)sel = ((u64)(u32)nliv << 32) | (u64)nkth; }
        } else if (act){
            overlap_work(s12, sc0, w1A, hbrow, rank16, idx, pacc, y1v, y2v, pn);
        }
        __syncthreads();                               // C: sel ready

        u64 nselv = *(const u64*)sel;
        bool fixp = (nch == 0) && (nselv == selv);     // identical in both CTAs
        selv = nselv;
        par ^= 1;
        if (fixp) break;                               // exact fixed point
    }

    // ---- outputs (rank 0 only): [cell | food | total | living] ----
    const u32 kthF = (u32)selv;
    const int livF = (int)(selv >> 32);
    float c0f = (act && bitsPrev >= kthF) ? c0pPrev : 0.f;

    if (rank == 0){
        if (act){
            int cb = (b*4)*NPIX + p;
            out[cb]           = c0f;
            out[cb +   NPIX]  = c1n;
            out[cb + 2*NPIX]  = c2n;
            out[cb + 3*NPIX]  = c3n;
            out[16*4*NPIX + b*NPIX + p] = food[b*NPIX + p];
        }
        float v = act ? c0f : 0.f;
        #pragma unroll
        for (int off = 16; off; off >>= 1) v += __shfl_down_sync(0xffffffffu, v, off);
        if ((tid & 31) == 0) wsum[tid >> 5] = v;
    }
    __syncthreads();
    if (rank == 0 && tid == 0){
        float t = 0.f;
        #pragma unroll
        for (int i = 0; i < 11; i++) t += wsum[i];
        out[23120 + b]      = t;
        out[23120 + 16 + b] = (float)livF;
    }
    CLUSTER_SYNC();   // no CTA exits while peer DSMEM traffic could be in flight
}

extern "C" void kernel_launch(void* const* d_in, const int* in_sizes, int n_in,
                              void* d_out, int out_size)
{
    const float* cell = (const float*)d_in[0];
    const float* food = (const float*)d_in[1];
    const float* fc1w = (const float*)d_in[3];
    const float* fc1b = (const float*)d_in[4];
    const float* fc2w = (const float*)d_in[5];
    const float* fc2b = (const float*)d_in[6];
    float* out = (float*)d_out;

    cudaFuncSetAttribute(ca_kernel, cudaFuncAttributeMaxDynamicSharedMemorySize, SMEM_BYTES);
    ca_kernel<<<32, NT, SMEM_BYTES>>>(cell, food, fc1w, fc1b, fc2w, fc2b, out);
}